// round 8
// baseline (speedup 1.0000x reference)
#include <cuda_runtime.h>
#include <cuda_bf16.h>
#include <math.h>

// Problem constants
#define BB 8
#define TT 2048
#define DD 1024
#define HH 16
#define DH 64
#define DI 1024          // H*DH
#define MROWS (BB*TT)    // 16384
#define SCH 8            // scan smem chunk (timesteps per barrier)
#define SROW 80          // padded scan row stride (4 blocks of 20 floats)

typedef unsigned long long ull;

// ---------------- scratch (no cudaMalloc allowed) ----------------
__device__ float g_xn[(size_t)MROWS * DD];
__device__ float g_q [(size_t)MROWS * DI];
__device__ float g_k [(size_t)MROWS * DI];
__device__ float g_v [(size_t)MROWS * DI];
__device__ float g_a [(size_t)MROWS * DI];
__device__ float g_mk[(size_t)MROWS * DI];
__device__ float g_kn[(size_t)MROWS * DI];
__device__ float g_beta[(size_t)BB * HH * TT];
__device__ float g_o [(size_t)MROWS * DI];
__device__ float g_wbpad[1024 * 128];   // Wb padded to N=128, tf32-rounded (pad stays 0)
__device__ float g_wq[1024 * 1024];
__device__ float g_wk[1024 * 1024];
__device__ float g_wv[1024 * 1024];
__device__ float g_wa[1024 * 1024];
__device__ float g_wo[1024 * 1024];

__device__ __forceinline__ float sigmoidf_(float x) { return 1.f / (1.f + expf(-x)); }

__device__ __forceinline__ float f2tf(float f) {
    unsigned u;
    asm("cvt.rna.tf32.f32 %0, %1;" : "=r"(u) : "f"(f));
    return __uint_as_float(u);
}

// ---------------- packed f32x2 helpers ----------------
__device__ __forceinline__ ull pack2_(float lo, float hi) {
    ull d; asm("mov.b64 %0, {%1, %2};" : "=l"(d) : "f"(lo), "f"(hi)); return d;
}
__device__ __forceinline__ ull fma2_(ull a, ull b, ull c) {
    ull d; asm("fma.rn.f32x2 %0, %1, %2, %3;" : "=l"(d) : "l"(a), "l"(b), "l"(c)); return d;
}
__device__ __forceinline__ ull mul2_(ull a, ull b) {
    ull d; asm("mul.rn.f32x2 %0, %1, %2;" : "=l"(d) : "l"(a), "l"(b)); return d;
}
__device__ __forceinline__ ull add2_(ull a, ull b) {
    ull d; asm("add.rn.f32x2 %0, %1, %2;" : "=l"(d) : "l"(a), "l"(b)); return d;
}
__device__ __forceinline__ float hadd2_(ull d) {
    float lo, hi; asm("mov.b64 {%0, %1}, %2;" : "=f"(lo), "=f"(hi) : "l"(d));
    return lo + hi;
}
__device__ __forceinline__ float red4_(ull a, ull b, ull c, ull d) {
    return hadd2_(add2_(add2_(a, b), add2_(c, d)));
}

// ---------------- cp.async helpers ----------------
#define CP_ASYNC16(dst_u32, src_ptr) \
    asm volatile("cp.async.cg.shared.global [%0], [%1], 16;" :: "r"(dst_u32), "l"(src_ptr))
#define CP_COMMIT() asm volatile("cp.async.commit_group;")
#define CP_WAIT_ALL() asm volatile("cp.async.wait_group 0;" ::: "memory")

// ---------------- fused prep: round 5 weight matrices + pack Wb ----------------
__global__ void __launch_bounds__(256) prep_kernel(
    const float* __restrict__ Wq, const float* __restrict__ Wk,
    const float* __restrict__ Wv, const float* __restrict__ Wa,
    const float* __restrict__ Wo, const float* __restrict__ Wb,
    float* __restrict__ wq, float* __restrict__ wk, float* __restrict__ wv,
    float* __restrict__ wa, float* __restrict__ wo, float* __restrict__ wbp)
{
    const int NM = 1024 * 1024 / 4;   // float4s per matrix
    int i = blockIdx.x * 256 + threadIdx.x;
    if (i < 5 * NM) {
        int m = i >> 18;              // / NM
        int j = i & (NM - 1);
        const float* src = (m == 0) ? Wq : (m == 1) ? Wk : (m == 2) ? Wv : (m == 3) ? Wa : Wo;
        float*       dst = (m == 0) ? wq : (m == 1) ? wk : (m == 2) ? wv : (m == 3) ? wa : wo;
        float4 v = ((const float4*)src)[j];
        v.x = f2tf(v.x); v.y = f2tf(v.y); v.z = f2tf(v.z); v.w = f2tf(v.w);
        ((float4*)dst)[j] = v;
    } else {
        int j = i - 5 * NM;           // 0..4095 float4s of Wb (1024x16)
        if (j < 4096) {
            float4 v = ((const float4*)Wb)[j];
            v.x = f2tf(v.x); v.y = f2tf(v.y); v.z = f2tf(v.z); v.w = f2tf(v.w);
            int kk = j >> 2, w = (j & 3) << 2;
            *(float4*)&wbp[kk * 128 + w] = v;
        }
    }
}

// ---------------- LayerNorm: one block per row of 1024, emits tf32 ----------------
__global__ void __launch_bounds__(256) ln_kernel(const float* __restrict__ x,
                                                 const float* __restrict__ g,
                                                 const float* __restrict__ b,
                                                 float* __restrict__ xn)
{
    int row = blockIdx.x;
    int tid = threadIdx.x;
    const float4* xr = (const float4*)(x + (size_t)row * DD);
    float4 v = xr[tid];
    float s  = v.x + v.y + v.z + v.w;
    float ss = v.x * v.x + v.y * v.y + v.z * v.z + v.w * v.w;
    #pragma unroll
    for (int o = 16; o > 0; o >>= 1) {
        s  += __shfl_xor_sync(0xffffffffu, s,  o);
        ss += __shfl_xor_sync(0xffffffffu, ss, o);
    }
    __shared__ float shs[8], shss[8];
    if ((tid & 31) == 0) { shs[tid >> 5] = s; shss[tid >> 5] = ss; }
    __syncthreads();
    s = 0.f; ss = 0.f;
    #pragma unroll
    for (int w = 0; w < 8; w++) { s += shs[w]; ss += shss[w]; }
    float mu   = s * (1.f / 1024.f);
    float var  = ss * (1.f / 1024.f) - mu * mu;
    float rstd = rsqrtf(var + 1e-5f);
    float4 gv = ((const float4*)g)[tid];
    float4 bv = ((const float4*)b)[tid];
    float4 o4;
    o4.x = f2tf((v.x - mu) * rstd * gv.x + bv.x);
    o4.y = f2tf((v.y - mu) * rstd * gv.y + bv.y);
    o4.z = f2tf((v.z - mu) * rstd * gv.z + bv.z);
    o4.w = f2tf((v.w - mu) * rstd * gv.w + bv.w);
    ((float4*)(xn + (size_t)row * DD))[tid] = o4;
}

// ---------------- TF32 tensor-core GEMM (mma.sync.m16n8k8, cp.async staging) ----
__global__ void __launch_bounds__(128, 2) tf32gemm_kernel(
    const float* __restrict__ A, const float* __restrict__ B,
    float* __restrict__ C, const float* __restrict__ bias,
    const float* __restrict__ resid, int N, int K, int mode)
{
    __shared__ __align__(16) float As[2][128][20];
    __shared__ __align__(16) float Bs[2][16][136];

    const int tid  = threadIdx.x;
    const int lane = tid & 31, warp = tid >> 5;
    const int wm = warp >> 1, wn = warp & 1;
    const int gid = lane >> 2, tig = lane & 3;
    const int mbase = blockIdx.y * 128, nbase = blockIdx.x * 128;

    const int ar  = tid >> 2;
    const int ac4 = (tid & 3) << 2;
    const int bk  = tid >> 5;
    const int bn  = (tid & 31) << 2;
    const float* Aptr = A + (size_t)(mbase + ar) * K + ac4;
    const float* Bptr = B + (size_t)bk * N + nbase + bn;

    unsigned sA[4], sB[4];
    #pragma unroll
    for (int s = 0; s < 4; s++) {
        sA[s] = (unsigned)__cvta_generic_to_shared(&As[0][ar + 32 * s][ac4]);
        sB[s] = (unsigned)__cvta_generic_to_shared(&Bs[0][bk + 4 * s][bn]);
    }
    const unsigned AOFF = 128 * 20 * 4;
    const unsigned BOFF = 16 * 136 * 4;

    float c[4][8][4];
    #pragma unroll
    for (int mi = 0; mi < 4; mi++)
        #pragma unroll
        for (int nj = 0; nj < 8; nj++)
            #pragma unroll
            for (int e = 0; e < 4; e++) c[mi][nj][e] = 0.f;

    #pragma unroll
    for (int s = 0; s < 4; s++) {
        CP_ASYNC16(sA[s], Aptr + (size_t)(32 * s) * K);
        CP_ASYNC16(sB[s], Bptr + (size_t)(4 * s) * N);
    }
    CP_COMMIT();
    Aptr += 16; Bptr += (size_t)16 * N;
    CP_WAIT_ALL();
    __syncthreads();

    const int nk = K >> 4;
    for (int it = 0; it < nk; ++it) {
        const int buf = it & 1;
        const bool pf = (it + 1 < nk);
        if (pf) {
            const unsigned ao = (buf ^ 1) * AOFF, bo = (buf ^ 1) * BOFF;
            #pragma unroll
            for (int s = 0; s < 4; s++) {
                CP_ASYNC16(sA[s] + ao, Aptr + (size_t)(32 * s) * K);
                CP_ASYNC16(sB[s] + bo, Bptr + (size_t)(4 * s) * N);
            }
            CP_COMMIT();
            Aptr += 16; Bptr += (size_t)16 * N;
        }
        #pragma unroll
        for (int ks = 0; ks < 2; ks++) {
            unsigned a[4][4], b[8][2];
            #pragma unroll
            for (int mi = 0; mi < 4; mi++) {
                const float* ap = &As[buf][wm * 64 + mi * 16 + gid][ks * 8 + tig];
                a[mi][0] = __float_as_uint(ap[0]);
                a[mi][1] = __float_as_uint(ap[8 * 20]);
                a[mi][2] = __float_as_uint(ap[4]);
                a[mi][3] = __float_as_uint(ap[8 * 20 + 4]);
            }
            #pragma unroll
            for (int nj = 0; nj < 8; nj++) {
                const float* bp = &Bs[buf][ks * 8 + tig][wn * 64 + nj * 8 + gid];
                b[nj][0] = __float_as_uint(bp[0]);
                b[nj][1] = __float_as_uint(bp[4 * 136]);
            }
            #pragma unroll
            for (int mi = 0; mi < 4; mi++)
                #pragma unroll
                for (int nj = 0; nj < 8; nj++)
                    asm volatile(
                        "mma.sync.aligned.m16n8k8.row.col.f32.tf32.tf32.f32 "
                        "{%0,%1,%2,%3}, {%4,%5,%6,%7}, {%8,%9}, {%0,%1,%2,%3};"
                        : "+f"(c[mi][nj][0]), "+f"(c[mi][nj][1]),
                          "+f"(c[mi][nj][2]), "+f"(c[mi][nj][3])
                        : "r"(a[mi][0]), "r"(a[mi][1]), "r"(a[mi][2]), "r"(a[mi][3]),
                          "r"(b[nj][0]), "r"(b[nj][1]));
        }
        if (pf) CP_WAIT_ALL();
        __syncthreads();
    }

    #pragma unroll
    for (int mi = 0; mi < 4; mi++) {
        #pragma unroll
        for (int half = 0; half < 2; half++) {
            int m = mbase + wm * 64 + mi * 16 + gid + half * 8;
            int bidx = m >> 11;
            int t    = m & 2047;
            #pragma unroll
            for (int nj = 0; nj < 8; nj++) {
                int n = nbase + wn * 64 + nj * 8 + tig * 2;
                float v0 = c[mi][nj][half * 2 + 0];
                float v1 = c[mi][nj][half * 2 + 1];
                if (mode == 0) {
                    int h = n >> 6, dh = n & 63;
                    *(float2*)&C[(((size_t)(bidx * HH + h)) * TT + t) * DH + dh] =
                        make_float2(v0, v1);
                } else if (mode == 1) {
                    int h = n >> 6, dh = n & 63;
                    *(float2*)&C[(((size_t)(bidx * HH + h)) * TT + t) * DH + dh] =
                        make_float2(sigmoidf_(v0 + bias[n]), sigmoidf_(v1 + bias[n + 1]));
                } else if (mode == 2) {
                    size_t idx = (size_t)m * N + n;
                    float2 rr = *(const float2*)&resid[idx];
                    *(float2*)&C[idx] = make_float2(v0 + rr.x, v1 + rr.y);
                } else {
                    if (n < 16) {
                        C[((size_t)(bidx * HH + n)) * TT + t]     = sigmoidf_(v0 + bias[n]);
                        C[((size_t)(bidx * HH + n + 1)) * TT + t] = sigmoidf_(v1 + bias[n + 1]);
                    }
                }
            }
        }
    }
}

// ---------------- scan_m: M recurrence -> raw Mk AND kn (=k*invk) to gmem ------
__global__ void __launch_bounds__(256, 1) scan_m_kernel(
    const float* __restrict__ kg, const float* __restrict__ raw_gamma,
    float* __restrict__ mkg, float* __restrict__ kng)
{
    int c = blockIdx.x;
    int h = c & 15;
    float gm = 1.f / (1.f + expf(-raw_gamma[h]));
    const ull gm2 = pack2_(gm, gm);

    int tid = threadIdx.x;
    int r = tid >> 2, cb = tid & 3;
    const int col0 = cb * 20;
    const int rIdx = (r >> 4) * 20 + (r & 15);

    __shared__ __align__(16) float sh_k[2][SCH][SROW];

    ull M2[8];
    #pragma unroll
    for (int j = 0; j < 8; j++) M2[j] = 0ull;
    if ((r >> 4) == cb) {
        int p = r & 15;
        M2[p >> 1] = (p & 1) ? pack2_(0.f, 1e-6f) : pack2_(1e-6f, 0.f);
    }

    const float* kp = kg + (size_t)c * TT * DH;
    float* mko = mkg + (size_t)c * TT * DH;
    float* kno = kng + (size_t)c * TT * DH;

    const int t8 = tid >> 4, f4 = (tid & 15) << 2;
    const int d4 = (f4 >> 4) * 20 + (f4 & 15);
    float4 pf;
    if (tid < 128) {
        pf = *(const float4*)(kp + t8 * 64 + f4);
        *(float4*)&sh_k[0][t8][d4] = pf;
    }
    __syncthreads();

    const int NCH = TT / SCH;
    for (int ch = 0; ch < NCH; ++ch) {
        const int buf = ch & 1;
        if (ch + 1 < NCH && tid < 128)
            pf = *(const float4*)(kp + (size_t)((ch + 1) * SCH + t8) * 64 + f4);

        #pragma unroll
        for (int tt = 0; tt < SCH; ++tt) {
            ull k2[8];
            #pragma unroll
            for (int jj = 0; jj < 8; jj += 2)
                *(ulonglong2*)(k2 + jj) = *(const ulonglong2*)(&sh_k[buf][tt][col0 + 2 * jj]);
            float kr = sh_k[buf][tt][rIdx];

            ull na = 0ull, nb = 0ull, nc = 0ull, nd = 0ull;
            na = fma2_(k2[0], k2[0], na); nb = fma2_(k2[1], k2[1], nb);
            nc = fma2_(k2[2], k2[2], nc); nd = fma2_(k2[3], k2[3], nd);
            na = fma2_(k2[4], k2[4], na); nb = fma2_(k2[5], k2[5], nb);
            nc = fma2_(k2[6], k2[6], nc); nd = fma2_(k2[7], k2[7], nd);
            float n2 = red4_(na, nb, nc, nd);
            n2 += __shfl_xor_sync(0xffffffffu, n2, 1);
            n2 += __shfl_xor_sync(0xffffffffu, n2, 2);
            float invk = rsqrtf(fmaxf(n2, 1e-24f));
            float coef = kr * invk * invk;
            const ull coef2 = pack2_(coef, coef);

            ull d0 = 0ull, d1 = 0ull, d2 = 0ull, d3 = 0ull;
            #pragma unroll
            for (int j = 0; j < 8; j += 4) {
                M2[j]     = fma2_(coef2, k2[j],     mul2_(gm2, M2[j]));
                M2[j + 1] = fma2_(coef2, k2[j + 1], mul2_(gm2, M2[j + 1]));
                M2[j + 2] = fma2_(coef2, k2[j + 2], mul2_(gm2, M2[j + 2]));
                M2[j + 3] = fma2_(coef2, k2[j + 3], mul2_(gm2, M2[j + 3]));
                d0 = fma2_(M2[j],     k2[j],     d0);
                d1 = fma2_(M2[j + 1], k2[j + 1], d1);
                d2 = fma2_(M2[j + 2], k2[j + 2], d2);
                d3 = fma2_(M2[j + 3], k2[j + 3], d3);
            }
            float mkp = red4_(d0, d1, d2, d3);
            mkp += __shfl_xor_sync(0xffffffffu, mkp, 1);
            mkp += __shfl_xor_sync(0xffffffffu, mkp, 2);
            if (cb == 0)
                mko[(size_t)(ch * SCH + tt) * DH + r] = mkp * invk;
            if (r == 0) {
                // 4 threads write kn[col0_logical .. +16) = k * invk
                const ull iv2 = pack2_(invk, invk);
                float* dst = kno + (size_t)(ch * SCH + tt) * DH + (cb << 4);
                ulonglong2 w0, w1, w2, w3;
                w0.x = mul2_(k2[0], iv2); w0.y = mul2_(k2[1], iv2);
                w1.x = mul2_(k2[2], iv2); w1.y = mul2_(k2[3], iv2);
                w2.x = mul2_(k2[4], iv2); w2.y = mul2_(k2[5], iv2);
                w3.x = mul2_(k2[6], iv2); w3.y = mul2_(k2[7], iv2);
                *(ulonglong2*)(dst)      = w0;
                *(ulonglong2*)(dst + 4)  = w1;
                *(ulonglong2*)(dst + 8)  = w2;
                *(ulonglong2*)(dst + 12) = w3;
            }
        }

        if (ch + 1 < NCH && tid < 128)
            *(float4*)&sh_k[buf ^ 1][t8][d4] = pf;
        __syncthreads();
    }
}

// ---------------- scan_s: S recurrence, e-split across 2 CTAs per chain --------
// grid = 256: blockIdx.x = chain*2 + e-half. 128 threads: local row r_loc=tid>>2
// (32 e-rows), cb=tid&3 (16 d-cols). e-columns of S are independent given the
// shared per-step vectors, so the two CTAs never communicate.
__global__ void __launch_bounds__(128, 2) scan_s_kernel(
    const float* __restrict__ qg, const float* __restrict__ kng,
    const float* __restrict__ vg, const float* __restrict__ ag,
    const float* __restrict__ mkg, const float* __restrict__ betag,
    float* __restrict__ og)
{
    int bid = blockIdx.x;
    int c = bid >> 1, eh = bid & 1;
    int bidx = c >> 4, h = c & 15;
    int tid = threadIdx.x;
    int r = (eh << 5) + (tid >> 2);     // global e-row 0..63
    int cb = tid & 3;
    const int col0 = cb * 20;
    const int rIdx = (r >> 4) * 20 + (r & 15);

    // arr: 0=kn 1=q 2=a 3=mk 4=v ; padded rows
    __shared__ __align__(16) float sh[2][5][SCH][SROW];
    __shared__ float sh_b[2][SCH];

    ull ST2[8];
    #pragma unroll
    for (int j = 0; j < 8; j++) ST2[j] = 0ull;

    size_t chbase = (size_t)c * TT * DH;
    const float* knp = kng + chbase;
    const float* qp  = qg  + chbase;
    const float* ap  = ag  + chbase;
    const float* mkp = mkg + chbase;
    const float* vp  = vg  + chbase;
    const float* bp  = betag + (size_t)c * TT;
    float* op = og + (size_t)bidx * TT * DI + h * DH;

    const int t8 = tid >> 4, f4 = (tid & 15) << 2;
    const int d4 = (f4 >> 4) * 20 + (f4 & 15);
    float4 p0, p1, p2v, p3, p4;
    float pbeta = 0.f;
    {
        size_t off = (size_t)t8 * 64 + f4;
        p0 = *(const float4*)(knp + off);
        p1 = *(const float4*)(qp  + off);
        p2v= *(const float4*)(ap  + off);
        p3 = *(const float4*)(mkp + off);
        p4 = *(const float4*)(vp  + off);
        *(float4*)&sh[0][0][t8][d4] = p0;
        *(float4*)&sh[0][1][t8][d4] = p1;
        *(float4*)&sh[0][2][t8][d4] = p2v;
        *(float4*)&sh[0][3][t8][d4] = p3;
        *(float4*)&sh[0][4][t8][d4] = p4;
    }
    if (tid >= 120) { pbeta = bp[tid - 120]; sh_b[0][tid - 120] = pbeta; }
    __syncthreads();

    const int NCH = TT / SCH;
    for (int ch = 0; ch < NCH; ++ch) {
        const int buf = ch & 1;
        if (ch + 1 < NCH) {
            size_t off = (size_t)((ch + 1) * SCH + t8) * 64 + f4;
            p0 = *(const float4*)(knp + off);
            p1 = *(const float4*)(qp  + off);
            p2v= *(const float4*)(ap  + off);
            p3 = *(const float4*)(mkp + off);
            p4 = *(const float4*)(vp  + off);
            if (tid >= 120) pbeta = bp[(ch + 1) * SCH + (tid - 120)];
        }

        #pragma unroll
        for (int tt = 0; tt < SCH; ++tt) {
            ull kn2[8], q2[8], a2[8], mk2[8];
            #pragma unroll
            for (int jj = 0; jj < 8; jj += 2) {
                *(ulonglong2*)(kn2 + jj) = *(const ulonglong2*)(&sh[buf][0][tt][col0 + 2 * jj]);
                *(ulonglong2*)(q2  + jj) = *(const ulonglong2*)(&sh[buf][1][tt][col0 + 2 * jj]);
                *(ulonglong2*)(a2  + jj) = *(const ulonglong2*)(&sh[buf][2][tt][col0 + 2 * jj]);
                *(ulonglong2*)(mk2 + jj) = *(const ulonglong2*)(&sh[buf][3][tt][col0 + 2 * jj]);
            }
            float vr  = sh[buf][4][tt][rIdx];
            float bet = sh_b[buf][tt];

            // ||Mk||^2 (local 16 cols + 2 shfls across cb groups)
            ull ma = 0ull, mb = 0ull;
            #pragma unroll
            for (int j = 0; j < 8; j += 2) {
                ma = fma2_(mk2[j],     mk2[j],     ma);
                mb = fma2_(mk2[j + 1], mk2[j + 1], mb);
            }
            float mn2 = hadd2_(add2_(ma, mb));
            mn2 += __shfl_xor_sync(0xffffffffu, mn2, 1);
            mn2 += __shfl_xor_sync(0xffffffffu, mn2, 2);
            float invmk = rsqrtf(fmaxf(mn2, 1e-12f));

            // kproj partial: p = sum_d ST * (a*kn)
            ull e0 = 0ull, e1 = 0ull, e2 = 0ull, e3 = 0ull;
            #pragma unroll
            for (int j = 0; j < 8; j += 4) {
                e0 = fma2_(ST2[j],     mul2_(a2[j],     kn2[j]),     e0);
                e1 = fma2_(ST2[j + 1], mul2_(a2[j + 1], kn2[j + 1]), e1);
                e2 = fma2_(ST2[j + 2], mul2_(a2[j + 2], kn2[j + 2]), e2);
                e3 = fma2_(ST2[j + 3], mul2_(a2[j + 3], kn2[j + 3]), e3);
            }
            float pp = red4_(e0, e1, e2, e3);
            pp += __shfl_xor_sync(0xffffffffu, pp, 1);
            pp += __shfl_xor_sync(0xffffffffu, pp, 2);

            float bu   = bet * vr;                 // b * v_e (kn already normalized)
            float nbpm = -(bet * pp * invmk);      // -b*kproj_e*invmk on raw Mk
            const ull bu2 = pack2_(bu, bu);
            const ull nb2 = pack2_(nbpm, nbpm);

            ull o0 = 0ull, o1 = 0ull, o2 = 0ull, o3 = 0ull;
            #pragma unroll
            for (int j = 0; j < 8; j += 4) {
                ull u0 = fma2_(bu2, kn2[j],     mul2_(nb2, mk2[j]));
                ull u1 = fma2_(bu2, kn2[j + 1], mul2_(nb2, mk2[j + 1]));
                ull u2 = fma2_(bu2, kn2[j + 2], mul2_(nb2, mk2[j + 2]));
                ull u3 = fma2_(bu2, kn2[j + 3], mul2_(nb2, mk2[j + 3]));
                ST2[j]     = fma2_(a2[j],     ST2[j],     u0);
                ST2[j + 1] = fma2_(a2[j + 1], ST2[j + 1], u1);
                ST2[j + 2] = fma2_(a2[j + 2], ST2[j + 2], u2);
                ST2[j + 3] = fma2_(a2[j + 3], ST2[j + 3], u3);
                o0 = fma2_(ST2[j],     q2[j],     o0);
                o1 = fma2_(ST2[j + 1], q2[j + 1], o1);
                o2 = fma2_(ST2[j + 2], q2[j + 2], o2);
                o3 = fma2_(ST2[j + 3], q2[j + 3], o3);
            }
            float po = red4_(o0, o1, o2, o3);
            po += __shfl_xor_sync(0xffffffffu, po, 1);
            po += __shfl_xor_sync(0xffffffffu, po, 2);
            if (cb == 0)
                op[(size_t)(ch * SCH + tt) * DI + r] = f2tf(po);
        }

        if (ch + 1 < NCH) {
            *(float4*)&sh[buf ^ 1][0][t8][d4] = p0;
            *(float4*)&sh[buf ^ 1][1][t8][d4] = p1;
            *(float4*)&sh[buf ^ 1][2][t8][d4] = p2v;
            *(float4*)&sh[buf ^ 1][3][t8][d4] = p3;
            *(float4*)&sh[buf ^ 1][4][t8][d4] = p4;
            if (tid >= 120) sh_b[buf ^ 1][tid - 120] = pbeta;
        }
        __syncthreads();
    }
}

// ---------------- launch ----------------
extern "C" void kernel_launch(void* const* d_in, const int* in_sizes, int n_in,
                              void* d_out, int out_size)
{
    (void)in_sizes; (void)n_in; (void)out_size;
    const float* x    = (const float*)d_in[0];
    const float* ln_g = (const float*)d_in[1];
    const float* ln_b = (const float*)d_in[2];
    const float* Wq   = (const float*)d_in[3];
    const float* Wk   = (const float*)d_in[4];
    const float* Wv   = (const float*)d_in[5];
    const float* Wa   = (const float*)d_in[6];
    const float* ba   = (const float*)d_in[7];
    const float* Wb   = (const float*)d_in[8];
    const float* bb   = (const float*)d_in[9];
    const float* rg   = (const float*)d_in[10];
    const float* Wo   = (const float*)d_in[11];
    float* out = (float*)d_out;

    float *xn, *q_, *k_, *v_, *a_, *mk_, *kn_, *bet, *o_, *wbp;
    float *wq, *wk, *wv, *wa, *wo;
    cudaGetSymbolAddress((void**)&xn,  g_xn);
    cudaGetSymbolAddress((void**)&q_,  g_q);
    cudaGetSymbolAddress((void**)&k_,  g_k);
    cudaGetSymbolAddress((void**)&v_,  g_v);
    cudaGetSymbolAddress((void**)&a_,  g_a);
    cudaGetSymbolAddress((void**)&mk_, g_mk);
    cudaGetSymbolAddress((void**)&kn_, g_kn);
    cudaGetSymbolAddress((void**)&bet, g_beta);
    cudaGetSymbolAddress((void**)&o_,  g_o);
    cudaGetSymbolAddress((void**)&wbp, g_wbpad);
    cudaGetSymbolAddress((void**)&wq,  g_wq);
    cudaGetSymbolAddress((void**)&wk,  g_wk);
    cudaGetSymbolAddress((void**)&wv,  g_wv);
    cudaGetSymbolAddress((void**)&wa,  g_wa);
    cudaGetSymbolAddress((void**)&wo,  g_wo);

    cudaStream_t s2;
    cudaStreamCreateWithFlags(&s2, cudaStreamNonBlocking);
    cudaEvent_t evK, evM;
    cudaEventCreateWithFlags(&evK, cudaEventDisableTiming);
    cudaEventCreateWithFlags(&evM, cudaEventDisableTiming);

    // 1: prep (rounds 5 weights + packs Wb)
    prep_kernel<<<(5 * 262144 + 4096 + 255) / 256, 256>>>(
        Wq, Wk, Wv, Wa, Wo, Wb, wq, wk, wv, wa, wo, wbp);
    // 2: layernorm
    ln_kernel<<<MROWS, 256>>>(x, ln_g, ln_b, xn);

    dim3 g1(DI / 128, MROWS / 128);   // (8, 128)
    // 3: K projection
    tf32gemm_kernel<<<g1, 128>>>(xn, wk, k_, nullptr, nullptr, DI, DD, 0);
    // fork: scan_m on side stream, concurrent with Q/V/A/beta GEMMs
    cudaEventRecord(evK, 0);
    cudaStreamWaitEvent(s2, evK, 0);
    // 4: scan_m (side stream)
    scan_m_kernel<<<BB * HH, 256, 0, s2>>>(k_, rg, mk_, kn_);
    cudaEventRecord(evM, s2);
    // 5..8: remaining projections (main stream)
    tf32gemm_kernel<<<g1, 128>>>(xn, wq, q_, nullptr, nullptr, DI, DD, 0);
    tf32gemm_kernel<<<g1, 128>>>(xn, wv, v_, nullptr, nullptr, DI, DD, 0);
    tf32gemm_kernel<<<g1, 128>>>(xn, wa, a_, ba,      nullptr, DI, DD, 1);
    tf32gemm_kernel<<<dim3(1, MROWS / 128), 128>>>(xn, wbp, bet, bb, nullptr, 128, DD, 3);
    // join
    cudaStreamWaitEvent(0, evM, 0);
    // 9: scan_s (e-split: 2 CTAs per chain)
    scan_s_kernel<<<2 * BB * HH, 128>>>(q_, kn_, v_, a_, mk_, bet, o_);
    // 10: output projection + residual
    tf32gemm_kernel<<<g1, 128>>>(o_, wo, out, nullptr, x, DD, DI, 2);
}

// round 9
// speedup vs baseline: 1.1981x; 1.1981x over previous
#include <cuda_runtime.h>
#include <cuda_bf16.h>
#include <math.h>

// Problem constants
#define BB 8
#define TT 2048
#define DD 1024
#define HH 16
#define DH 64
#define DI 1024          // H*DH
#define MROWS (BB*TT)    // 16384
#define SCH 8            // scan smem chunk (timesteps per barrier)
#define SROW 80          // padded scan row stride (4 blocks of 20 floats)

typedef unsigned long long ull;

// ---------------- scratch (no cudaMalloc allowed) ----------------
__device__ float g_xn[(size_t)MROWS * DD];
__device__ float g_q [(size_t)MROWS * DI];
__device__ float g_k [(size_t)MROWS * DI];
__device__ float g_v [(size_t)MROWS * DI];
__device__ float g_a [(size_t)MROWS * DI];
__device__ float g_mk[(size_t)MROWS * DI];
__device__ float g_kn[(size_t)MROWS * DI];
__device__ float g_beta[(size_t)BB * HH * TT];
__device__ float g_o [(size_t)MROWS * DI];
__device__ float g_wbpad[1024 * 128];   // Wb padded to N=128, tf32-rounded (pad stays 0)
__device__ float g_wq[1024 * 1024];
__device__ float g_wk[1024 * 1024];
__device__ float g_wv[1024 * 1024];
__device__ float g_wa[1024 * 1024];
__device__ float g_wo[1024 * 1024];

__device__ __forceinline__ float sigmoidf_(float x) { return 1.f / (1.f + expf(-x)); }

__device__ __forceinline__ float f2tf(float f) {
    unsigned u;
    asm("cvt.rna.tf32.f32 %0, %1;" : "=r"(u) : "f"(f));
    return __uint_as_float(u);
}

// ---------------- packed f32x2 helpers ----------------
__device__ __forceinline__ ull pack2_(float lo, float hi) {
    ull d; asm("mov.b64 %0, {%1, %2};" : "=l"(d) : "f"(lo), "f"(hi)); return d;
}
__device__ __forceinline__ ull fma2_(ull a, ull b, ull c) {
    ull d; asm("fma.rn.f32x2 %0, %1, %2, %3;" : "=l"(d) : "l"(a), "l"(b), "l"(c)); return d;
}
__device__ __forceinline__ ull mul2_(ull a, ull b) {
    ull d; asm("mul.rn.f32x2 %0, %1, %2;" : "=l"(d) : "l"(a), "l"(b)); return d;
}
__device__ __forceinline__ ull add2_(ull a, ull b) {
    ull d; asm("add.rn.f32x2 %0, %1, %2;" : "=l"(d) : "l"(a), "l"(b)); return d;
}
__device__ __forceinline__ float hadd2_(ull d) {
    float lo, hi; asm("mov.b64 {%0, %1}, %2;" : "=f"(lo), "=f"(hi) : "l"(d));
    return lo + hi;
}
__device__ __forceinline__ float red4_(ull a, ull b, ull c, ull d) {
    return hadd2_(add2_(add2_(a, b), add2_(c, d)));
}

// ---------------- cp.async helpers ----------------
#define CP_ASYNC16(dst_u32, src_ptr) \
    asm volatile("cp.async.cg.shared.global [%0], [%1], 16;" :: "r"(dst_u32), "l"(src_ptr))
#define CP_COMMIT() asm volatile("cp.async.commit_group;")
#define CP_WAIT_ALL() asm volatile("cp.async.wait_group 0;" ::: "memory")

// ---------------- fused prep: round 5 weight matrices + pack Wb ----------------
__global__ void __launch_bounds__(256) prep_kernel(
    const float* __restrict__ Wq, const float* __restrict__ Wk,
    const float* __restrict__ Wv, const float* __restrict__ Wa,
    const float* __restrict__ Wo, const float* __restrict__ Wb,
    float* __restrict__ wq, float* __restrict__ wk, float* __restrict__ wv,
    float* __restrict__ wa, float* __restrict__ wo, float* __restrict__ wbp)
{
    const int NM = 1024 * 1024 / 4;   // float4s per matrix
    int i = blockIdx.x * 256 + threadIdx.x;
    if (i < 5 * NM) {
        int m = i >> 18;              // / NM
        int j = i & (NM - 1);
        const float* src = (m == 0) ? Wq : (m == 1) ? Wk : (m == 2) ? Wv : (m == 3) ? Wa : Wo;
        float*       dst = (m == 0) ? wq : (m == 1) ? wk : (m == 2) ? wv : (m == 3) ? wa : wo;
        float4 v = ((const float4*)src)[j];
        v.x = f2tf(v.x); v.y = f2tf(v.y); v.z = f2tf(v.z); v.w = f2tf(v.w);
        ((float4*)dst)[j] = v;
    } else {
        int j = i - 5 * NM;           // 0..4095 float4s of Wb (1024x16)
        if (j < 4096) {
            float4 v = ((const float4*)Wb)[j];
            v.x = f2tf(v.x); v.y = f2tf(v.y); v.z = f2tf(v.z); v.w = f2tf(v.w);
            int kk = j >> 2, w = (j & 3) << 2;
            *(float4*)&wbp[kk * 128 + w] = v;
        }
    }
}

// ---------------- LayerNorm: one block per row of 1024, emits tf32 ----------------
__global__ void __launch_bounds__(256) ln_kernel(const float* __restrict__ x,
                                                 const float* __restrict__ g,
                                                 const float* __restrict__ b,
                                                 float* __restrict__ xn)
{
    int row = blockIdx.x;
    int tid = threadIdx.x;
    const float4* xr = (const float4*)(x + (size_t)row * DD);
    float4 v = xr[tid];
    float s  = v.x + v.y + v.z + v.w;
    float ss = v.x * v.x + v.y * v.y + v.z * v.z + v.w * v.w;
    #pragma unroll
    for (int o = 16; o > 0; o >>= 1) {
        s  += __shfl_xor_sync(0xffffffffu, s,  o);
        ss += __shfl_xor_sync(0xffffffffu, ss, o);
    }
    __shared__ float shs[8], shss[8];
    if ((tid & 31) == 0) { shs[tid >> 5] = s; shss[tid >> 5] = ss; }
    __syncthreads();
    s = 0.f; ss = 0.f;
    #pragma unroll
    for (int w = 0; w < 8; w++) { s += shs[w]; ss += shss[w]; }
    float mu   = s * (1.f / 1024.f);
    float var  = ss * (1.f / 1024.f) - mu * mu;
    float rstd = rsqrtf(var + 1e-5f);
    float4 gv = ((const float4*)g)[tid];
    float4 bv = ((const float4*)b)[tid];
    float4 o4;
    o4.x = f2tf((v.x - mu) * rstd * gv.x + bv.x);
    o4.y = f2tf((v.y - mu) * rstd * gv.y + bv.y);
    o4.z = f2tf((v.z - mu) * rstd * gv.z + bv.z);
    o4.w = f2tf((v.w - mu) * rstd * gv.w + bv.w);
    ((float4*)(xn + (size_t)row * DD))[tid] = o4;
}

// ---------------- knorm: parallel row-normalize k -> kn = k/max(||k||,eps) -----
// 16 threads per 64-float row; fully parallel over 128*2048 rows.
__global__ void __launch_bounds__(256) knorm_kernel(
    const float* __restrict__ kg, float* __restrict__ kng, int nrows)
{
    int gid = blockIdx.x * 256 + threadIdx.x;
    int row = gid >> 4;               // 16 threads per row
    if (row >= nrows) return;
    int p = gid & 15;
    const float4* src = (const float4*)(kg + (size_t)row * DH);
    float4 v = src[p];
    float ss = v.x * v.x + v.y * v.y + v.z * v.z + v.w * v.w;
    ss += __shfl_xor_sync(0xffffffffu, ss, 1);
    ss += __shfl_xor_sync(0xffffffffu, ss, 2);
    ss += __shfl_xor_sync(0xffffffffu, ss, 4);
    ss += __shfl_xor_sync(0xffffffffu, ss, 8);
    float inv = rsqrtf(fmaxf(ss, 1e-24f));
    float4 o;
    o.x = v.x * inv; o.y = v.y * inv; o.z = v.z * inv; o.w = v.w * inv;
    ((float4*)(kng + (size_t)row * DH))[p] = o;
}

// ---------------- TF32 tensor-core GEMM (mma.sync.m16n8k8, cp.async staging) ----
__global__ void __launch_bounds__(128, 2) tf32gemm_kernel(
    const float* __restrict__ A, const float* __restrict__ B,
    float* __restrict__ C, const float* __restrict__ bias,
    const float* __restrict__ resid, int N, int K, int mode)
{
    __shared__ __align__(16) float As[2][128][20];
    __shared__ __align__(16) float Bs[2][16][136];

    const int tid  = threadIdx.x;
    const int lane = tid & 31, warp = tid >> 5;
    const int wm = warp >> 1, wn = warp & 1;
    const int gid = lane >> 2, tig = lane & 3;
    const int mbase = blockIdx.y * 128, nbase = blockIdx.x * 128;

    const int ar  = tid >> 2;
    const int ac4 = (tid & 3) << 2;
    const int bk  = tid >> 5;
    const int bn  = (tid & 31) << 2;
    const float* Aptr = A + (size_t)(mbase + ar) * K + ac4;
    const float* Bptr = B + (size_t)bk * N + nbase + bn;

    unsigned sA[4], sB[4];
    #pragma unroll
    for (int s = 0; s < 4; s++) {
        sA[s] = (unsigned)__cvta_generic_to_shared(&As[0][ar + 32 * s][ac4]);
        sB[s] = (unsigned)__cvta_generic_to_shared(&Bs[0][bk + 4 * s][bn]);
    }
    const unsigned AOFF = 128 * 20 * 4;
    const unsigned BOFF = 16 * 136 * 4;

    float c[4][8][4];
    #pragma unroll
    for (int mi = 0; mi < 4; mi++)
        #pragma unroll
        for (int nj = 0; nj < 8; nj++)
            #pragma unroll
            for (int e = 0; e < 4; e++) c[mi][nj][e] = 0.f;

    #pragma unroll
    for (int s = 0; s < 4; s++) {
        CP_ASYNC16(sA[s], Aptr + (size_t)(32 * s) * K);
        CP_ASYNC16(sB[s], Bptr + (size_t)(4 * s) * N);
    }
    CP_COMMIT();
    Aptr += 16; Bptr += (size_t)16 * N;
    CP_WAIT_ALL();
    __syncthreads();

    const int nk = K >> 4;
    for (int it = 0; it < nk; ++it) {
        const int buf = it & 1;
        const bool pf = (it + 1 < nk);
        if (pf) {
            const unsigned ao = (buf ^ 1) * AOFF, bo = (buf ^ 1) * BOFF;
            #pragma unroll
            for (int s = 0; s < 4; s++) {
                CP_ASYNC16(sA[s] + ao, Aptr + (size_t)(32 * s) * K);
                CP_ASYNC16(sB[s] + bo, Bptr + (size_t)(4 * s) * N);
            }
            CP_COMMIT();
            Aptr += 16; Bptr += (size_t)16 * N;
        }
        #pragma unroll
        for (int ks = 0; ks < 2; ks++) {
            unsigned a[4][4], b[8][2];
            #pragma unroll
            for (int mi = 0; mi < 4; mi++) {
                const float* ap = &As[buf][wm * 64 + mi * 16 + gid][ks * 8 + tig];
                a[mi][0] = __float_as_uint(ap[0]);
                a[mi][1] = __float_as_uint(ap[8 * 20]);
                a[mi][2] = __float_as_uint(ap[4]);
                a[mi][3] = __float_as_uint(ap[8 * 20 + 4]);
            }
            #pragma unroll
            for (int nj = 0; nj < 8; nj++) {
                const float* bp = &Bs[buf][ks * 8 + tig][wn * 64 + nj * 8 + gid];
                b[nj][0] = __float_as_uint(bp[0]);
                b[nj][1] = __float_as_uint(bp[4 * 136]);
            }
            #pragma unroll
            for (int mi = 0; mi < 4; mi++)
                #pragma unroll
                for (int nj = 0; nj < 8; nj++)
                    asm volatile(
                        "mma.sync.aligned.m16n8k8.row.col.f32.tf32.tf32.f32 "
                        "{%0,%1,%2,%3}, {%4,%5,%6,%7}, {%8,%9}, {%0,%1,%2,%3};"
                        : "+f"(c[mi][nj][0]), "+f"(c[mi][nj][1]),
                          "+f"(c[mi][nj][2]), "+f"(c[mi][nj][3])
                        : "r"(a[mi][0]), "r"(a[mi][1]), "r"(a[mi][2]), "r"(a[mi][3]),
                          "r"(b[nj][0]), "r"(b[nj][1]));
        }
        if (pf) CP_WAIT_ALL();
        __syncthreads();
    }

    #pragma unroll
    for (int mi = 0; mi < 4; mi++) {
        #pragma unroll
        for (int half = 0; half < 2; half++) {
            int m = mbase + wm * 64 + mi * 16 + gid + half * 8;
            int bidx = m >> 11;
            int t    = m & 2047;
            #pragma unroll
            for (int nj = 0; nj < 8; nj++) {
                int n = nbase + wn * 64 + nj * 8 + tig * 2;
                float v0 = c[mi][nj][half * 2 + 0];
                float v1 = c[mi][nj][half * 2 + 1];
                if (mode == 0) {
                    int h = n >> 6, dh = n & 63;
                    *(float2*)&C[(((size_t)(bidx * HH + h)) * TT + t) * DH + dh] =
                        make_float2(v0, v1);
                } else if (mode == 1) {
                    int h = n >> 6, dh = n & 63;
                    *(float2*)&C[(((size_t)(bidx * HH + h)) * TT + t) * DH + dh] =
                        make_float2(sigmoidf_(v0 + bias[n]), sigmoidf_(v1 + bias[n + 1]));
                } else if (mode == 2) {
                    size_t idx = (size_t)m * N + n;
                    float2 rr = *(const float2*)&resid[idx];
                    *(float2*)&C[idx] = make_float2(v0 + rr.x, v1 + rr.y);
                } else {
                    if (n < 16) {
                        C[((size_t)(bidx * HH + n)) * TT + t]     = sigmoidf_(v0 + bias[n]);
                        C[((size_t)(bidx * HH + n + 1)) * TT + t] = sigmoidf_(v1 + bias[n + 1]);
                    }
                }
            }
        }
    }
}

// ---------------- scan_m: M recurrence on pre-normalized kn -> raw Mk ---------
// With kn input: coef = kn_r (no norm computation at all in the loop).
__global__ void __launch_bounds__(256, 1) scan_m_kernel(
    const float* __restrict__ kng, const float* __restrict__ raw_gamma,
    float* __restrict__ mkg)
{
    int c = blockIdx.x;
    int h = c & 15;
    float gm = 1.f / (1.f + expf(-raw_gamma[h]));
    const ull gm2 = pack2_(gm, gm);

    int tid = threadIdx.x;
    int r = tid >> 2, cb = tid & 3;
    const int col0 = cb * 20;
    const int rIdx = (r >> 4) * 20 + (r & 15);

    __shared__ __align__(16) float sh_k[2][SCH][SROW];

    ull M2[8];
    #pragma unroll
    for (int j = 0; j < 8; j++) M2[j] = 0ull;
    if ((r >> 4) == cb) {
        int p = r & 15;
        M2[p >> 1] = (p & 1) ? pack2_(0.f, 1e-6f) : pack2_(1e-6f, 0.f);
    }

    const float* kp = kng + (size_t)c * TT * DH;
    float* mko = mkg + (size_t)c * TT * DH;

    const int t8 = tid >> 4, f4 = (tid & 15) << 2;
    const int d4 = (f4 >> 4) * 20 + (f4 & 15);
    float4 pf;
    if (tid < 128) {
        pf = *(const float4*)(kp + t8 * 64 + f4);
        *(float4*)&sh_k[0][t8][d4] = pf;
    }
    __syncthreads();

    const int NCH = TT / SCH;
    for (int ch = 0; ch < NCH; ++ch) {
        const int buf = ch & 1;
        if (ch + 1 < NCH && tid < 128)
            pf = *(const float4*)(kp + (size_t)((ch + 1) * SCH + t8) * 64 + f4);

        #pragma unroll
        for (int tt = 0; tt < SCH; ++tt) {
            ull k2[8];
            #pragma unroll
            for (int jj = 0; jj < 8; jj += 2)
                *(ulonglong2*)(k2 + jj) = *(const ulonglong2*)(&sh_k[buf][tt][col0 + 2 * jj]);
            float kr = sh_k[buf][tt][rIdx];
            const ull coef2 = pack2_(kr, kr);

            ull d0 = 0ull, d1 = 0ull, d2 = 0ull, d3 = 0ull;
            #pragma unroll
            for (int j = 0; j < 8; j += 4) {
                M2[j]     = fma2_(coef2, k2[j],     mul2_(gm2, M2[j]));
                M2[j + 1] = fma2_(coef2, k2[j + 1], mul2_(gm2, M2[j + 1]));
                M2[j + 2] = fma2_(coef2, k2[j + 2], mul2_(gm2, M2[j + 2]));
                M2[j + 3] = fma2_(coef2, k2[j + 3], mul2_(gm2, M2[j + 3]));
                d0 = fma2_(M2[j],     k2[j],     d0);
                d1 = fma2_(M2[j + 1], k2[j + 1], d1);
                d2 = fma2_(M2[j + 2], k2[j + 2], d2);
                d3 = fma2_(M2[j + 3], k2[j + 3], d3);
            }
            float mkp = red4_(d0, d1, d2, d3);
            mkp += __shfl_xor_sync(0xffffffffu, mkp, 1);
            mkp += __shfl_xor_sync(0xffffffffu, mkp, 2);
            if (cb == 0)
                mko[(size_t)(ch * SCH + tt) * DH + r] = mkp;
        }

        if (ch + 1 < NCH && tid < 128)
            *(float4*)&sh_k[buf ^ 1][t8][d4] = pf;
        __syncthreads();
    }
}

// ---------------- scan_s: S recurrence, e-split across 2 CTAs per chain --------
__global__ void __launch_bounds__(128, 2) scan_s_kernel(
    const float* __restrict__ qg, const float* __restrict__ kng,
    const float* __restrict__ vg, const float* __restrict__ ag,
    const float* __restrict__ mkg, const float* __restrict__ betag,
    float* __restrict__ og)
{
    int bid = blockIdx.x;
    int c = bid >> 1, eh = bid & 1;
    int bidx = c >> 4, h = c & 15;
    int tid = threadIdx.x;
    int r = (eh << 5) + (tid >> 2);     // global e-row 0..63
    int cb = tid & 3;
    const int col0 = cb * 20;
    const int rIdx = (r >> 4) * 20 + (r & 15);

    // arr: 0=kn 1=q 2=a 3=mk 4=v ; padded rows
    __shared__ __align__(16) float sh[2][5][SCH][SROW];
    __shared__ float sh_b[2][SCH];

    ull ST2[8];
    #pragma unroll
    for (int j = 0; j < 8; j++) ST2[j] = 0ull;

    size_t chbase = (size_t)c * TT * DH;
    const float* knp = kng + chbase;
    const float* qp  = qg  + chbase;
    const float* ap  = ag  + chbase;
    const float* mkp = mkg + chbase;
    const float* vp  = vg  + chbase;
    const float* bp  = betag + (size_t)c * TT;
    float* op = og + (size_t)bidx * TT * DI + h * DH;

    const int t8 = tid >> 4, f4 = (tid & 15) << 2;
    const int d4 = (f4 >> 4) * 20 + (f4 & 15);
    float4 p0, p1, p2v, p3, p4;
    float pbeta = 0.f;
    {
        size_t off = (size_t)t8 * 64 + f4;
        p0 = *(const float4*)(knp + off);
        p1 = *(const float4*)(qp  + off);
        p2v= *(const float4*)(ap  + off);
        p3 = *(const float4*)(mkp + off);
        p4 = *(const float4*)(vp  + off);
        *(float4*)&sh[0][0][t8][d4] = p0;
        *(float4*)&sh[0][1][t8][d4] = p1;
        *(float4*)&sh[0][2][t8][d4] = p2v;
        *(float4*)&sh[0][3][t8][d4] = p3;
        *(float4*)&sh[0][4][t8][d4] = p4;
    }
    if (tid >= 120) { pbeta = bp[tid - 120]; sh_b[0][tid - 120] = pbeta; }
    __syncthreads();

    const int NCH = TT / SCH;
    for (int ch = 0; ch < NCH; ++ch) {
        const int buf = ch & 1;
        if (ch + 1 < NCH) {
            size_t off = (size_t)((ch + 1) * SCH + t8) * 64 + f4;
            p0 = *(const float4*)(knp + off);
            p1 = *(const float4*)(qp  + off);
            p2v= *(const float4*)(ap  + off);
            p3 = *(const float4*)(mkp + off);
            p4 = *(const float4*)(vp  + off);
            if (tid >= 120) pbeta = bp[(ch + 1) * SCH + (tid - 120)];
        }

        #pragma unroll
        for (int tt = 0; tt < SCH; ++tt) {
            ull kn2[8], q2[8], a2[8], mk2[8];
            #pragma unroll
            for (int jj = 0; jj < 8; jj += 2) {
                *(ulonglong2*)(kn2 + jj) = *(const ulonglong2*)(&sh[buf][0][tt][col0 + 2 * jj]);
                *(ulonglong2*)(q2  + jj) = *(const ulonglong2*)(&sh[buf][1][tt][col0 + 2 * jj]);
                *(ulonglong2*)(a2  + jj) = *(const ulonglong2*)(&sh[buf][2][tt][col0 + 2 * jj]);
                *(ulonglong2*)(mk2 + jj) = *(const ulonglong2*)(&sh[buf][3][tt][col0 + 2 * jj]);
            }
            float vr  = sh[buf][4][tt][rIdx];
            float bet = sh_b[buf][tt];

            // ||Mk||^2 (local 16 cols + 2 shfls across cb groups)
            ull ma = 0ull, mb = 0ull;
            #pragma unroll
            for (int j = 0; j < 8; j += 2) {
                ma = fma2_(mk2[j],     mk2[j],     ma);
                mb = fma2_(mk2[j + 1], mk2[j + 1], mb);
            }
            float mn2 = hadd2_(add2_(ma, mb));
            mn2 += __shfl_xor_sync(0xffffffffu, mn2, 1);
            mn2 += __shfl_xor_sync(0xffffffffu, mn2, 2);
            float invmk = rsqrtf(fmaxf(mn2, 1e-12f));

            // kproj partial: p = sum_d ST * (a*kn)
            ull e0 = 0ull, e1 = 0ull, e2 = 0ull, e3 = 0ull;
            #pragma unroll
            for (int j = 0; j < 8; j += 4) {
                e0 = fma2_(ST2[j],     mul2_(a2[j],     kn2[j]),     e0);
                e1 = fma2_(ST2[j + 1], mul2_(a2[j + 1], kn2[j + 1]), e1);
                e2 = fma2_(ST2[j + 2], mul2_(a2[j + 2], kn2[j + 2]), e2);
                e3 = fma2_(ST2[j + 3], mul2_(a2[j + 3], kn2[j + 3]), e3);
            }
            float pp = red4_(e0, e1, e2, e3);
            pp += __shfl_xor_sync(0xffffffffu, pp, 1);
            pp += __shfl_xor_sync(0xffffffffu, pp, 2);

            float bu   = bet * vr;                 // b * v_e (kn already normalized)
            float nbpm = -(bet * pp * invmk);      // -b*kproj_e*invmk on raw Mk
            const ull bu2 = pack2_(bu, bu);
            const ull nb2 = pack2_(nbpm, nbpm);

            ull o0 = 0ull, o1 = 0ull, o2 = 0ull, o3 = 0ull;
            #pragma unroll
            for (int j = 0; j < 8; j += 4) {
                ull u0 = fma2_(bu2, kn2[j],     mul2_(nb2, mk2[j]));
                ull u1 = fma2_(bu2, kn2[j + 1], mul2_(nb2, mk2[j + 1]));
                ull u2 = fma2_(bu2, kn2[j + 2], mul2_(nb2, mk2[j + 2]));
                ull u3 = fma2_(bu2, kn2[j + 3], mul2_(nb2, mk2[j + 3]));
                ST2[j]     = fma2_(a2[j],     ST2[j],     u0);
                ST2[j + 1] = fma2_(a2[j + 1], ST2[j + 1], u1);
                ST2[j + 2] = fma2_(a2[j + 2], ST2[j + 2], u2);
                ST2[j + 3] = fma2_(a2[j + 3], ST2[j + 3], u3);
                o0 = fma2_(ST2[j],     q2[j],     o0);
                o1 = fma2_(ST2[j + 1], q2[j + 1], o1);
                o2 = fma2_(ST2[j + 2], q2[j + 2], o2);
                o3 = fma2_(ST2[j + 3], q2[j + 3], o3);
            }
            float po = red4_(o0, o1, o2, o3);
            po += __shfl_xor_sync(0xffffffffu, po, 1);
            po += __shfl_xor_sync(0xffffffffu, po, 2);
            if (cb == 0)
                op[(size_t)(ch * SCH + tt) * DI + r] = f2tf(po);
        }

        if (ch + 1 < NCH) {
            *(float4*)&sh[buf ^ 1][0][t8][d4] = p0;
            *(float4*)&sh[buf ^ 1][1][t8][d4] = p1;
            *(float4*)&sh[buf ^ 1][2][t8][d4] = p2v;
            *(float4*)&sh[buf ^ 1][3][t8][d4] = p3;
            *(float4*)&sh[buf ^ 1][4][t8][d4] = p4;
            if (tid >= 120) sh_b[buf ^ 1][tid - 120] = pbeta;
        }
        __syncthreads();
    }
}

// ---------------- launch ----------------
extern "C" void kernel_launch(void* const* d_in, const int* in_sizes, int n_in,
                              void* d_out, int out_size)
{
    (void)in_sizes; (void)n_in; (void)out_size;
    const float* x    = (const float*)d_in[0];
    const float* ln_g = (const float*)d_in[1];
    const float* ln_b = (const float*)d_in[2];
    const float* Wq   = (const float*)d_in[3];
    const float* Wk   = (const float*)d_in[4];
    const float* Wv   = (const float*)d_in[5];
    const float* Wa   = (const float*)d_in[6];
    const float* ba   = (const float*)d_in[7];
    const float* Wb   = (const float*)d_in[8];
    const float* bb   = (const float*)d_in[9];
    const float* rg   = (const float*)d_in[10];
    const float* Wo   = (const float*)d_in[11];
    float* out = (float*)d_out;

    float *xn, *q_, *k_, *v_, *a_, *mk_, *kn_, *bet, *o_, *wbp;
    float *wq, *wk, *wv, *wa, *wo;
    cudaGetSymbolAddress((void**)&xn,  g_xn);
    cudaGetSymbolAddress((void**)&q_,  g_q);
    cudaGetSymbolAddress((void**)&k_,  g_k);
    cudaGetSymbolAddress((void**)&v_,  g_v);
    cudaGetSymbolAddress((void**)&a_,  g_a);
    cudaGetSymbolAddress((void**)&mk_, g_mk);
    cudaGetSymbolAddress((void**)&kn_, g_kn);
    cudaGetSymbolAddress((void**)&bet, g_beta);
    cudaGetSymbolAddress((void**)&o_,  g_o);
    cudaGetSymbolAddress((void**)&wbp, g_wbpad);
    cudaGetSymbolAddress((void**)&wq,  g_wq);
    cudaGetSymbolAddress((void**)&wk,  g_wk);
    cudaGetSymbolAddress((void**)&wv,  g_wv);
    cudaGetSymbolAddress((void**)&wa,  g_wa);
    cudaGetSymbolAddress((void**)&wo,  g_wo);

    cudaStream_t s2;
    cudaStreamCreateWithFlags(&s2, cudaStreamNonBlocking);
    cudaEvent_t evK, evM;
    cudaEventCreateWithFlags(&evK, cudaEventDisableTiming);
    cudaEventCreateWithFlags(&evM, cudaEventDisableTiming);

    // 1: prep (rounds 5 weights + packs Wb)
    prep_kernel<<<(5 * 262144 + 4096 + 255) / 256, 256>>>(
        Wq, Wk, Wv, Wa, Wo, Wb, wq, wk, wv, wa, wo, wbp);
    // 2: layernorm
    ln_kernel<<<MROWS, 256>>>(x, ln_g, ln_b, xn);

    dim3 g1(DI / 128, MROWS / 128);   // (8, 128)
    // 3: K projection
    tf32gemm_kernel<<<g1, 128>>>(xn, wk, k_, nullptr, nullptr, DI, DD, 0);
    // fork: knorm + scan_m on side stream, concurrent with Q/V/A/beta GEMMs
    cudaEventRecord(evK, 0);
    cudaStreamWaitEvent(s2, evK, 0);
    // 4: knorm (side stream, parallel)
    knorm_kernel<<<(128 * TT * 16 + 255) / 256, 256, 0, s2>>>(k_, kn_, 128 * TT);
    // 5: scan_m (side stream, consumes kn)
    scan_m_kernel<<<BB * HH, 256, 0, s2>>>(kn_, rg, mk_);
    cudaEventRecord(evM, s2);
    // 6..9: remaining projections (main stream)
    tf32gemm_kernel<<<g1, 128>>>(xn, wq, q_, nullptr, nullptr, DI, DD, 0);
    tf32gemm_kernel<<<g1, 128>>>(xn, wv, v_, nullptr, nullptr, DI, DD, 0);
    tf32gemm_kernel<<<g1, 128>>>(xn, wa, a_, ba,      nullptr, DI, DD, 1);
    tf32gemm_kernel<<<dim3(1, MROWS / 128), 128>>>(xn, wbp, bet, bb, nullptr, 128, DD, 3);
    // join
    cudaStreamWaitEvent(0, evM, 0);
    // 10: scan_s (e-split: 2 CTAs per chain)
    scan_s_kernel<<<2 * BB * HH, 128>>>(q_, kn_, v_, a_, mk_, bet, o_);
    // 11: output projection + residual
    tf32gemm_kernel<<<g1, 128>>>(o_, wo, out, nullptr, x, DD, DI, 2);
}